// round 12
// baseline (speedup 1.0000x reference)
#include <cuda_runtime.h>
#include <cstdint>

// Problem constants
#define TT 16384
#define HH 100
#define HE 104          // extended h: [h(100), x0, x1, x2, 1]
#define UC 50           // units per CTA
#define NT 100          // threads per CTA

// Hidden states [t][u]
__device__ float g_hs[TT * HH];

// ---------------------------------------------------------------------------
__device__ __forceinline__ float2 ffma2(float2 a, float2 b, float2 c) {
    float2 r;
    asm("fma.rn.f32x2 %0, %1, %2, %3;"
        : "=l"(reinterpret_cast<unsigned long long&>(r))
        : "l"(reinterpret_cast<unsigned long long&>(a)),
          "l"(reinterpret_cast<unsigned long long&>(b)),
          "l"(reinterpret_cast<unsigned long long&>(c)));
    return r;
}
__device__ __forceinline__ float2 fadd2(float2 a, float2 b) {
    float2 r;
    asm("add.rn.f32x2 %0, %1, %2;"
        : "=l"(reinterpret_cast<unsigned long long&>(r))
        : "l"(reinterpret_cast<unsigned long long&>(a)),
          "l"(reinterpret_cast<unsigned long long&>(b)));
    return r;
}
__device__ __forceinline__ float tanh_approx(float x) {
    float r; asm("tanh.approx.f32 %0, %1;" : "=f"(r) : "f"(x)); return r;
}
__device__ __forceinline__ float ex2_approx(float x) {
    float r; asm("ex2.approx.f32 %0, %1;" : "=f"(r) : "f"(x)); return r;
}
__device__ __forceinline__ float rcp_approx(float x) {
    float r; asm("rcp.approx.f32 %0, %1;" : "=f"(r) : "f"(x)); return r;
}

#define LOG2E 1.4426950408889634f

// --- cluster / mbarrier primitives -----------------------------------------
__device__ __forceinline__ uint32_t smem_u32(const void* p) {
    uint32_t a;
    asm("{ .reg .u64 t; cvta.to.shared.u64 t, %1; cvt.u32.u64 %0, t; }"
        : "=r"(a) : "l"(p));
    return a;
}
__device__ __forceinline__ uint32_t my_rank() {
    uint32_t r; asm("mov.u32 %0, %%cluster_ctarank;" : "=r"(r)); return r;
}
__device__ __forceinline__ uint32_t mapa_peer(uint32_t local, uint32_t rank) {
    uint32_t r;
    asm("mapa.shared::cluster.u32 %0, %1, %2;" : "=r"(r) : "r"(local), "r"(rank));
    return r;
}
__device__ __forceinline__ void st_cluster_f32(uint32_t addr, float v) {
    asm volatile("st.shared::cluster.f32 [%0], %1;" :: "r"(addr), "f"(v) : "memory");
}
__device__ __forceinline__ void mbar_init(uint32_t a, uint32_t cnt) {
    asm volatile("mbarrier.init.shared.b64 [%0], %1;" :: "r"(a), "r"(cnt) : "memory");
}
__device__ __forceinline__ void mbar_arrive_peer(uint32_t a) {
    asm volatile("mbarrier.arrive.release.cluster.shared::cluster.b64 _, [%0];"
                 :: "r"(a) : "memory");
}
__device__ __forceinline__ void mbar_wait_parity(uint32_t a, uint32_t par) {
    asm volatile(
        "{\n\t"
        ".reg .pred P;\n\t"
        "W%=:\n\t"
        "mbarrier.try_wait.parity.acquire.cluster.shared::cta.b64 P, [%0], %1;\n\t"
        "@P bra D%=;\n\t"
        "bra W%=;\n\t"
        "D%=:\n\t"
        "}"
        :: "r"(a), "r"(par) : "memory");
}
#define CLUSTER_SYNC() do { \
    asm volatile("barrier.cluster.arrive.aligned;" ::: "memory"); \
    asm volatile("barrier.cluster.wait.aligned;" ::: "memory"); \
} while (0)

// ---------------------------------------------------------------------------
// 2-CTA-cluster LSTM: CTA r owns units [50r, 50r+50). 100 threads/CTA,
// pair structure (even: i,f rows; odd: g,o rows) with 104-wide extended
// weight rows [Whh | Wih | bias] so the dot product computes the full
// preactivation from h~ = [h, x_t, 1]. Per step each CTA writes its 50 h
// values into BOTH CTAs' double buffers (local STS + st.shared::cluster),
// even threads arrive on the PEER's mbarrier (release.cluster, count=50),
// __syncthreads, then parity-wait (acquire.cluster) on the OWN mbarrier.
// Halves the per-SM FMA issue load (the R9 bottleneck) for ~100 cyc sync.
// ---------------------------------------------------------------------------
__global__ void __launch_bounds__(NT, 1) __cluster_dims__(2, 1, 1)
k_lstm_cluster(const float* __restrict__ x,
               const float* __restrict__ Whh,
               const float* __restrict__ Wih,
               const float* __restrict__ bih,
               const float* __restrict__ bhh,
               const float* __restrict__ Wlin,
               const float* __restrict__ blin,
               float* __restrict__ out) {
    extern __shared__ __align__(16) float sx[];        // [TT*3] input table
    __shared__ __align__(16) float sh[2][HE];          // extended h, 2 buffers
    __shared__ __align__(8) unsigned long long mbar;
    __shared__ float sWl[HH];
    __shared__ float sbl;

    const int tid  = threadIdx.x;        // 0..99
    const int odd  = tid & 1;
    const int ul   = tid >> 1;           // local unit 0..49
    const uint32_t rank = my_rank();
    const int ug   = (int)rank * UC + ul;    // global unit
    const unsigned mask = (tid >= 96) ? 0x0000000Fu : 0xFFFFFFFFu;

    const int r0 = odd * 2 * HH + ug;    // even: i-row, odd: g-row
    const int r1 = r0 + HH;              // even: f-row, odd: o-row

    // slot0 act = A0*tanh(S0*g)+B0: even sigmoid(.5,.5,.5), odd tanh(1,1,0)
    const float S0 = odd ? 1.0f : 0.5f;
    const float A0 = odd ? 1.0f : 0.5f;
    const float B0 = odd ? 0.0f : 0.5f;

    // Extended weight rows: [Whh(100) | Wih(3) | bias]  (52 float2 each)
    float2 w0[52], w1[52];
    {
        #pragma unroll
        for (int j = 0; j < 52; j++) {
            int k0 = 2 * j, k1 = 2 * j + 1;
            float a0v, a1v, b0v, b1v;
            a0v = (k0 < HH) ? Whh[r0 * HH + k0]
                : (k0 < 103) ? Wih[r0 * 3 + (k0 - HH)] : (bih[r0] + bhh[r0]);
            a1v = (k1 < HH) ? Whh[r0 * HH + k1]
                : (k1 < 103) ? Wih[r0 * 3 + (k1 - HH)] : (bih[r0] + bhh[r0]);
            b0v = (k0 < HH) ? Whh[r1 * HH + k0]
                : (k0 < 103) ? Wih[r1 * 3 + (k0 - HH)] : (bih[r1] + bhh[r1]);
            b1v = (k1 < HH) ? Whh[r1 * HH + k1]
                : (k1 < 103) ? Wih[r1 * 3 + (k1 - HH)] : (bih[r1] + bhh[r1]);
            w0[j] = make_float2(a0v, a1v);
            w1[j] = make_float2(b0v, b1v);
        }
    }

    // Preload x table; stage W_lin; init h buffers and mbarrier
    {
        const float4* xs = reinterpret_cast<const float4*>(x);
        float4* xd = reinterpret_cast<float4*>(sx);
        for (int i = tid; i < TT * 3 / 4; i += NT) xd[i] = xs[i];
    }
    if (tid < HH) sWl[tid] = Wlin[tid];
    if (tid < HH) { sh[0][tid] = 0.0f; sh[1][tid] = 0.0f; }
    if (tid == 0) {
        sbl = blin[0];
        sh[0][103] = 1.0f; sh[1][103] = 1.0f;
        mbar_init(smem_u32(&mbar), UC);
    }
    __syncthreads();
    if (tid < 3) sh[0][100 + tid] = sx[tid];   // x(0) into buffer 0
    __syncthreads();
    CLUSTER_SYNC();   // both CTAs' mbarriers + buffers ready

    // Cross-CTA addresses (computed once)
    const uint32_t mbarL    = smem_u32(&mbar);
    const uint32_t peerMbar = mapa_peer(mbarL, rank ^ 1u);
    const uint32_t peerH0   = mapa_peer(smem_u32(&sh[0][ug]), rank ^ 1u);
    const uint32_t peerH1   = mapa_peer(smem_u32(&sh[1][ug]), rank ^ 1u);

    float c = 0.0f;

    #pragma unroll 1
    for (int t = 0; t < TT; t++) {
        const int rb = t & 1;
        const float4* hp = reinterpret_cast<const float4*>(&sh[rb][0]);

        // Dual 104-wide dot products (preactivation incl. x and bias):
        // 26 broadcast LDS.128 + 104 FFMA2 in 4 independent chains
        float2 a00 = make_float2(0.0f, 0.0f), a01 = make_float2(0.0f, 0.0f);
        float2 a10 = make_float2(0.0f, 0.0f), a11 = make_float2(0.0f, 0.0f);
        #pragma unroll
        for (int i = 0; i < 26; i++) {
            float4 hv = hp[i];
            float2 lo = make_float2(hv.x, hv.y);
            float2 hi = make_float2(hv.z, hv.w);
            a00 = ffma2(lo, w0[2 * i],     a00);
            a01 = ffma2(hi, w0[2 * i + 1], a01);
            a10 = ffma2(lo, w1[2 * i],     a10);
            a11 = ffma2(hi, w1[2 * i + 1], a11);
        }
        float2 s0 = fadd2(a00, a01);
        float2 s1 = fadd2(a10, a11);
        float gt0 = s0.x + s0.y;
        float gt1 = s1.x + s1.y;

        // Activations (single MUFU.TANH each)
        float a0 = fmaf(A0, tanh_approx(S0 * gt0), B0);
        float a1 = fmaf(0.5f, tanh_approx(0.5f * gt1), 0.5f);

        // Pair exchange
        float p0 = __shfl_xor_sync(mask, a0, 1);
        float p1 = __shfl_xor_sync(mask, a1, 1);
        float ai = odd ? p0 : a0;
        float af = odd ? p1 : a1;
        float ag = odd ? a0 : p0;
        float ao = odd ? a1 : p1;

        // Replicated c/h update
        c = fmaf(af, c, ai * ag);
        float hn = ao * tanh_approx(c);

        if (!odd) {
            sh[rb ^ 1][ug] = hn;                       // local buffer
            st_cluster_f32(rb ? peerH0 : peerH1, hn);  // peer buffer
            g_hs[t * HH + ug] = hn;
            mbar_arrive_peer(peerMbar);                // release.cluster
        } else if (tid < 7) {
            // threads 1,3,5 stage x(t+1) into the write buffer
            int j = tid >> 1;                          // 0,1,2
            int tn = (t + 1 < TT) ? (t + 1) : t;
            sh[rb ^ 1][100 + j] = sx[3 * tn + j];
        }
        __syncthreads();            // local h/x visible; legalizes next phase
        mbar_wait_parity(mbarL, (uint32_t)(t & 1));    // peer half arrived
    }

    // ---- projection: CTA r handles its half of the timesteps ----
    __threadfence();
    CLUSTER_SYNC();
    const float bl = sbl;
    const int tbase = (int)rank * (TT / 2);
    for (int t = tbase + tid; t < tbase + TT / 2; t += NT) {
        const float4* hr = reinterpret_cast<const float4*>(g_hs + t * HH);
        float s0 = 0.0f, s1 = 0.0f;
        #pragma unroll
        for (int j = 0; j < 25; j++) {
            float4 hv = hr[j];
            const float* wl = sWl + 4 * j;
            s0 = fmaf(hv.x, wl[0], s0);
            s1 = fmaf(hv.y, wl[1], s1);
            s0 = fmaf(hv.z, wl[2], s0);
            s1 = fmaf(hv.w, wl[3], s1);
        }
        float z = s0 + s1 + bl;
        out[t] = rcp_approx(1.0f + ex2_approx(-LOG2E * z));
    }
}

// ---------------------------------------------------------------------------
// Launch.  Inputs: input_x, W_ih, W_hh, b_ih, b_hh, W_lin, b_lin
// ---------------------------------------------------------------------------
extern "C" void kernel_launch(void* const* d_in, const int* in_sizes, int n_in,
                              void* d_out, int out_size) {
    const float* x    = (const float*)d_in[0];
    const float* Wih  = (const float*)d_in[1];
    const float* Whh  = (const float*)d_in[2];
    const float* bih  = (const float*)d_in[3];
    const float* bhh  = (const float*)d_in[4];
    const float* Wlin = (const float*)d_in[5];
    const float* blin = (const float*)d_in[6];
    float* out = (float*)d_out;

    (void)in_sizes; (void)n_in; (void)out_size;

    const int smem_bytes = TT * 3 * (int)sizeof(float);   // 192 KB (x table)
    static bool attr_set = false;
    if (!attr_set) {
        cudaFuncSetAttribute(k_lstm_cluster,
                             cudaFuncAttributeMaxDynamicSharedMemorySize,
                             smem_bytes);
        attr_set = true;
    }

    k_lstm_cluster<<<2, NT, smem_bytes>>>(x, Whh, Wih, bih, bhh,
                                          Wlin, blin, out);
}